// round 8
// baseline (speedup 1.0000x reference)
#include <cuda_runtime.h>
#include <cuda_fp16.h>
#include <math.h>
#include <stdint.h>

// Problem constants
#define Bq   8
#define Nq   8192
#define Cq   256
#define Hq   8
#define Dq   32
#define Sq   32
#define HIDq 1024
#define Mq   (Bq * Nq)        // 65536 rows
#define BHq  (Bq * Hq)        // 64
#define KV_CHUNKS 64          // one chunk per 128-token softkv CTA
#define QKVW 768              // fused q/k/v logit width

// GEMM tiling (fp16 mma m16n8k16)
#define BM 128
#define BN 128
#define BKH 64                          // K-halves per tile (128 bytes/row)
#define STAGE_BYTES (2 * BM * BKH * 2)  // A tile + B tile = 32KB
#define GEMM_SMEM (2 * STAGE_BYTES)     // 2 stages = 64KB

// ---------------- scratch (static device arrays; no allocation) -------------
__device__ __half g_xln_h[Mq * Cq];
__device__ __half g_qkv  [(size_t)Mq * QKVW];           // q|k|v logits; q normalized in place
__device__ float  g_ekvp [KV_CHUNKS * BHq * Sq * Dq];   // per-chunk partial kv
__device__ float  g_csp  [KV_CHUNKS * BHq * Sq];        // per-chunk col sums
__device__ __half g_KW   [Bq * Cq * Cq];                // KW[b][c][h*32+s]
__device__ float  g_h    [Mq * Cq];
__device__ __half g_y_h  [Mq * Cq];
__device__ __half g_hid_h[Mq * HIDq];
__device__ __half g_WQKV [QKVW * Cq];                   // composite weights
__device__ float  g_bqkv [QKVW];                        // composite biases
__device__ __half g_W1_h [HIDq * Cq];
__device__ __half g_W2_h [Cq * HIDq];

// ------------------------------ PTX helpers ---------------------------------
__device__ __forceinline__ uint32_t smem_u32(const void* p) {
    uint32_t a;
    asm("{ .reg .u64 t; cvta.to.shared.u64 t, %1; cvt.u32.u64 %0, t; }"
        : "=r"(a) : "l"(p));
    return a;
}
__device__ __forceinline__ void cp_async16(uint32_t dst, const void* src) {
    asm volatile("cp.async.ca.shared.global [%0], [%1], 16;"
                 :: "r"(dst), "l"(src));
}
__device__ __forceinline__ void cp_commit() {
    asm volatile("cp.async.commit_group;");
}
template <int N>
__device__ __forceinline__ void cp_wait() {
    asm volatile("cp.async.wait_group %0;" :: "n"(N));
}
__device__ __forceinline__ void ldsm4(uint32_t* r, uint32_t addr) {
    asm volatile("ldmatrix.sync.aligned.m8n8.x4.shared.b16 {%0,%1,%2,%3}, [%4];"
                 : "=r"(r[0]), "=r"(r[1]), "=r"(r[2]), "=r"(r[3]) : "r"(addr));
}
__device__ __forceinline__ void mma_f16(float* c, const uint32_t* a, const uint32_t* b) {
    asm volatile(
        "mma.sync.aligned.m16n8k16.row.col.f32.f16.f16.f32 "
        "{%0,%1,%2,%3}, {%4,%5,%6,%7}, {%8,%9}, {%0,%1,%2,%3};"
        : "+f"(c[0]), "+f"(c[1]), "+f"(c[2]), "+f"(c[3])
        : "r"(a[0]), "r"(a[1]), "r"(a[2]), "r"(a[3]), "r"(b[0]), "r"(b[1]));
}

// ---------------- fp32 -> fp16 weight conversion (one launch) ----------------
#define F4_W1 (HIDq * Cq / 4)          // 65536
#define F4_W2 (Cq * HIDq / 4)          // 65536
#define F4_TOTAL (F4_W1 + F4_W2)

__global__ void f2h_all_kernel(const float* __restrict__ W1,
                               const float* __restrict__ W2,
                               __half* oW1, __half* oW2) {
    int i = blockIdx.x * 256 + threadIdx.x;
    if (i >= F4_TOTAL) return;
    const float* src; __half* dst; int j;
    if (i < F4_W1) { src = W1; dst = oW1; j = i; }
    else           { src = W2; dst = oW2; j = i - F4_W1; }
    float4 v = ((const float4*)src)[j];
    ((__half2*)dst)[j * 2]     = __floats2half2_rn(v.x, v.y);
    ((__half2*)dst)[j * 2 + 1] = __floats2half2_rn(v.z, v.w);
}

// ------- composite weights: WQ~[h*32+s,:] = sum_d Wq[s,d] * Wx[h*32+d,:] ----
__global__ __launch_bounds__(256) void compose_kernel(
    const float* __restrict__ Wq, const float* __restrict__ Wk,
    const float* __restrict__ Wv, const float* __restrict__ Wx,
    const float* __restrict__ bx,
    __half* __restrict__ WQKV, float* __restrict__ bqkv) {
    int type = blockIdx.x >> 3;    // 0=q,1=k,2=v
    int h    = blockIdx.x & 7;
    const float* Wsm_g = (type == 0) ? Wq : (type == 1) ? Wk : Wv;
    __shared__ float Wsm[32][32];
    __shared__ float bxs[32];
    int tid = threadIdx.x;
    for (int i = tid; i < 1024; i += 256) Wsm[i >> 5][i & 31] = Wsm_g[i];
    if (tid < 32) bxs[tid] = bx[h * 32 + tid];
    __syncthreads();

    int j = tid;
    float xc[32];
#pragma unroll
    for (int d = 0; d < 32; d++) xc[d] = Wx[(size_t)(h * 32 + d) * Cq + j];
#pragma unroll
    for (int s = 0; s < 32; s++) {
        float a = 0.f;
#pragma unroll
        for (int d = 0; d < 32; d++) a += Wsm[s][d] * xc[d];
        WQKV[(size_t)(type * 256 + h * 32 + s) * Cq + j] = __float2half_rn(a);
    }
    if (tid < 32) {
        float a = 0.f;
#pragma unroll
        for (int d = 0; d < 32; d++) a += Wsm[tid][d] * bxs[d];
        bqkv[type * 256 + h * 32 + tid] = a;
    }
}

// ---------------- LayerNorm: one warp per row (C=256), fp16 out -------------
__global__ void ln_kernel(const float* __restrict__ x,
                          const float* __restrict__ w,
                          const float* __restrict__ bb,
                          __half* __restrict__ out) {
    int row  = blockIdx.x * 8 + threadIdx.y;
    int lane = threadIdx.x;
    const float* xr = x + (size_t)row * Cq;
    float v[8];
    float s = 0.f, s2 = 0.f;
#pragma unroll
    for (int i = 0; i < 8; i++) {
        float t = xr[lane + i * 32];
        v[i] = t; s += t; s2 += t * t;
    }
#pragma unroll
    for (int o = 16; o > 0; o >>= 1) {
        s  += __shfl_xor_sync(0xffffffffu, s,  o);
        s2 += __shfl_xor_sync(0xffffffffu, s2, o);
    }
    float mu  = s * (1.f / Cq);
    float var = s2 * (1.f / Cq) - mu * mu;
    float rs  = rsqrtf(var + 1e-5f);
    __half* orow = out + (size_t)row * Cq;
#pragma unroll
    for (int i = 0; i < 8; i++) {
        int c = lane + i * 32;
        orow[c] = __float2half_rn((v[i] - mu) * rs * w[c] + bb[c]);
    }
}

// ------------- fp16 mma GEMM: C = A[M,K] @ W[Ncols,K]^T + bias --------------
__device__ __forceinline__ float gelu_exact(float v) {
    return 0.5f * v * (1.f + erff(v * 0.70710678118654752f));
}

template <int EPI, int OUT16>
__global__ __launch_bounds__(256) void hgemm_kernel(
    const __half* __restrict__ A, const __half* __restrict__ W,
    const float* __restrict__ bias, const float* __restrict__ res,
    float* __restrict__ Cout, __half* __restrict__ Cout16,
    int Ncols, int K, int lda, size_t sA, size_t sW, size_t sC) {
    extern __shared__ char smem[];
    int tid  = threadIdx.x;
    int wid  = tid >> 5, lane = tid & 31;
    int g = lane >> 2, q = lane & 3;
    int warp_m = wid >> 2;
    int warp_n = wid & 3;
    size_t zoffC = sC * blockIdx.z;

    uint32_t sbase = smem_u32(smem);
    const __half* Ab = A + sA * blockIdx.z + (size_t)blockIdx.y * BM * lda;
    const __half* Wb = W + sW * blockIdx.z + (size_t)blockIdx.x * BN * K;

    float acc[4][4][4];
#pragma unroll
    for (int mt = 0; mt < 4; mt++)
#pragma unroll
        for (int nt = 0; nt < 4; nt++)
#pragma unroll
            for (int i = 0; i < 4; i++) acc[mt][nt][i] = 0.f;

    int ntiles = K / BKH;

    auto load_tile = [&](int stage, int kt) {
        uint32_t aoff = sbase + stage * STAGE_BYTES;
        uint32_t boff = aoff + BM * BKH * 2;
        int k0 = kt * BKH;
#pragma unroll
        for (int i = 0; i < 4; i++) {
            int idx  = i * 256 + tid;
            int row  = idx >> 3;
            int grp  = idx & 7;
            int phys = grp ^ (row & 7);
            cp_async16(aoff + (row * 8 + phys) * 16, &Ab[(size_t)row * lda + k0 + grp * 8]);
            cp_async16(boff + (row * 8 + phys) * 16, &Wb[(size_t)row * K + k0 + grp * 8]);
        }
    };

    load_tile(0, 0);
    cp_commit();

    for (int kt = 0; kt < ntiles; kt++) {
        int cur = kt & 1;
        if (kt + 1 < ntiles) {
            load_tile(cur ^ 1, kt + 1);
            cp_commit();
            cp_wait<1>();
        } else {
            cp_wait<0>();
        }
        __syncthreads();

        uint32_t sAb = sbase + cur * STAGE_BYTES;
        uint32_t sBb = sAb + BM * BKH * 2;

#pragma unroll
        for (int ks = 0; ks < 4; ks++) {
            uint32_t af[4][4];
#pragma unroll
            for (int mt = 0; mt < 4; mt++) {
                int row = warp_m * 64 + mt * 16 + (lane & 15);
                int kg  = 2 * ks + (lane >> 4);
                ldsm4(af[mt], sAb + (row * 8 + (kg ^ (row & 7))) * 16);
            }
            uint32_t bf[2][4];
#pragma unroll
            for (int p = 0; p < 2; p++) {
                int n  = warp_n * 32 + p * 16 + (lane >> 4) * 8 + (lane & 7);
                int kg = 2 * ks + ((lane >> 3) & 1);
                ldsm4(bf[p], sBb + (n * 8 + (kg ^ (n & 7))) * 16);
            }
#pragma unroll
            for (int mt = 0; mt < 4; mt++)
#pragma unroll
                for (int nt = 0; nt < 4; nt++)
                    mma_f16(acc[mt][nt], af[mt], &bf[nt >> 1][(nt & 1) * 2]);
        }
        __syncthreads();
    }

    int mBase = blockIdx.y * BM + warp_m * 64;
    int nBase = blockIdx.x * BN + warp_n * 32;
#pragma unroll
    for (int nt = 0; nt < 4; nt++) {
        int c0 = nBase + nt * 8 + q * 2;
        float bv0 = bias[c0], bv1 = bias[c0 + 1];
#pragma unroll
        for (int mt = 0; mt < 4; mt++) {
            int r0 = mBase + mt * 16 + g;
#pragma unroll
            for (int half = 0; half < 2; half++) {
                int r = r0 + half * 8;
                size_t off = (size_t)r * Ncols + c0 + zoffC;
                float v0 = acc[mt][nt][half * 2 + 0] + bv0;
                float v1 = acc[mt][nt][half * 2 + 1] + bv1;
                if (EPI == 1) {
                    float2 rr = *(const float2*)&res[off];
                    v0 += rr.x; v1 += rr.y;
                }
                if (EPI == 2) { v0 = gelu_exact(v0); v1 = gelu_exact(v1); }
                if (OUT16) {
                    *(__half2*)&Cout16[off] = __floats2half2_rn(v0, v1);
                } else {
                    *(float2*)&Cout[off] = make_float2(v0, v1);
                }
            }
        }
    }
}

// ------- softkv: q softmax in-place + kv partial via tensor-core mma --------
// CTA = (chunk of 128 tokens, head h, batch b), 128 threads, thread = token.
#define PADK 136   // halfs per smem row: 17 x 16B units -> ldmatrix conflict-free

__global__ __launch_bounds__(128) void softkv_kernel(__half* __restrict__ qkv) {
    __shared__ __half ekT[32][PADK];   // ek transposed: [s][token]
    __shared__ __half vT [48][PADK];   // v transposed: [d][token]; row32=1, 33..47=0
    int tid = threadIdx.x;
    int wrp = tid >> 5, lane = tid & 31;
    int ch = blockIdx.x, h = blockIdx.y, b = blockIdx.z;
    int n0 = ch * 128;
    int bh = b * Hq + h;

    // init vT rows 32..47 (ones row + zero pad)
    for (int i = tid; i < 16 * PADK; i += 128) {
        int r = i / PADK, c = i % PADK;
        vT[32 + r][c] = (r == 0 && c < 128) ? __float2half(1.f) : __half(0);
    }

    __half* row = qkv + ((size_t)(b * Nq + n0 + tid)) * QKVW;

    // --- q: softmax over 32 slices, normalized in place ---
    {
        __half2* qp = (__half2*)(row + h * 32);
        __half2 eh[16];
        float ssum = 0.f;
#pragma unroll
        for (int i = 0; i < 16; i++) {
            float2 f = __half22float2(qp[i]);
            float e0 = expf(f.x), e1 = expf(f.y);
            ssum += e0 + e1;
            eh[i] = __floats2half2_rn(e0, e1);
        }
        float r = 1.f / ssum;
#pragma unroll
        for (int i = 0; i < 16; i++) {
            float2 f = __half22float2(eh[i]);
            qp[i] = __floats2half2_rn(f.x * r, f.y * r);
        }
    }
    // --- k: ek = exp(logits) -> ekT[s][tid] ---
    {
        const __half2* kp = (const __half2*)(row + 256 + h * 32);
#pragma unroll
        for (int i = 0; i < 16; i++) {
            float2 f = __half22float2(kp[i]);
            ekT[2 * i][tid]     = __float2half_rn(expf(f.x));
            ekT[2 * i + 1][tid] = __float2half_rn(expf(f.y));
        }
    }
    // --- v -> vT[d][tid] ---
    {
        const __half2* vp = (const __half2*)(row + 512 + h * 32);
#pragma unroll
        for (int i = 0; i < 16; i++) {
            __half2 vv = vp[i];
            vT[2 * i][tid]     = __low2half(vv);
            vT[2 * i + 1][tid] = __high2half(vv);
        }
    }
    __syncthreads();

    // --- warp 0: kv_partial[32 s x 40 (32 d + colsum + pad)] = ekT @ vT^T ---
    if (wrp == 0) {
        uint32_t ek_base = smem_u32(ekT);
        uint32_t v_base  = smem_u32(vT);
        float acc[2][5][4];
#pragma unroll
        for (int mt = 0; mt < 2; mt++)
#pragma unroll
            for (int nt = 0; nt < 5; nt++)
#pragma unroll
                for (int i = 0; i < 4; i++) acc[mt][nt][i] = 0.f;

#pragma unroll
        for (int ks = 0; ks < 8; ks++) {
            uint32_t af[2][4];
#pragma unroll
            for (int mt = 0; mt < 2; mt++) {
                int r_ = mt * 16 + (lane & 15);
                int kg = 2 * ks + (lane >> 4);
                ldsm4(af[mt], ek_base + (r_ * PADK + kg * 8) * 2);
            }
            uint32_t bf[3][4];
#pragma unroll
            for (int p = 0; p < 3; p++) {
                int n_ = p * 16 + (lane >> 4) * 8 + (lane & 7);
                int kg = 2 * ks + ((lane >> 3) & 1);
                ldsm4(bf[p], v_base + (n_ * PADK + kg * 8) * 2);
            }
#pragma unroll
            for (int mt = 0; mt < 2; mt++)
#pragma unroll
                for (int nt = 0; nt < 5; nt++)
                    mma_f16(acc[mt][nt], af[mt], &bf[nt >> 1][(nt & 1) * 2]);
        }

        int g = lane >> 2, q = lane & 3;
        size_t pbase = ((size_t)ch * BHq + bh) * (Sq * Dq);
#pragma unroll
        for (int mt = 0; mt < 2; mt++) {
#pragma unroll
            for (int half = 0; half < 2; half++) {
                int s = mt * 16 + g + half * 8;
#pragma unroll
                for (int nt = 0; nt < 4; nt++) {
                    int d = nt * 8 + q * 2;
                    *(float2*)&g_ekvp[pbase + s * 32 + d] =
                        make_float2(acc[mt][nt][half * 2], acc[mt][nt][half * 2 + 1]);
                }
                if (q == 0)   // column 32 = ones column = token sum of ek
                    g_csp[((size_t)ch * BHq + bh) * Sq + s] = acc[mt][4][half * 2];
            }
        }
    }
}

// ---- kv finalize + KW = kv @ Wo_h^T  (fp16 [b][c][h*32+s]) ------------------
__global__ __launch_bounds__(256) void kvw_kernel(const float* __restrict__ Wo,
                                                  __half* __restrict__ KW) {
    int bh = blockIdx.x;
    int b = bh >> 3, h = bh & 7;
    int tid = threadIdx.x;
    __shared__ float kvs[32][33];
    __shared__ float rcs[32];

    if (tid < 32) {
        float c = 0.f;
#pragma unroll
        for (int ch = 0; ch < KV_CHUNKS; ch++)
            c += g_csp[((size_t)ch * BHq + bh) * Sq + tid];
        rcs[tid] = 1.f / c;
    }
    __syncthreads();
#pragma unroll
    for (int rep = 0; rep < 4; rep++) {
        int idx = tid + rep * 256;
        int s = idx >> 5, d = idx & 31;
        float vsum = 0.f;
#pragma unroll
        for (int ch = 0; ch < KV_CHUNKS; ch++)
            vsum += g_ekvp[((size_t)ch * BHq + bh) * (Sq * Dq) + idx];
        kvs[s][d] = vsum * rcs[s];
    }
    __syncthreads();

    int c = tid;
    float wo[32];
#pragma unroll
    for (int d = 0; d < 32; d++) wo[d] = Wo[(size_t)c * Cq + h * 32 + d];
    __half2 outv[16];
#pragma unroll
    for (int sp = 0; sp < 16; sp++) {
        float a0 = 0.f, a1 = 0.f;
#pragma unroll
        for (int d = 0; d < 32; d++) {
            a0 += kvs[2 * sp][d] * wo[d];
            a1 += kvs[2 * sp + 1][d] * wo[d];
        }
        outv[sp] = __floats2half2_rn(a0, a1);
    }
    uint4* dst = (uint4*)&KW[((size_t)b * Cq + c) * Cq + h * 32];
#pragma unroll
    for (int i = 0; i < 4; i++) dst[i] = ((uint4*)outv)[i];
}

// ---------------------------- launcher ---------------------------------------
extern "C" void kernel_launch(void* const* d_in, const int* in_sizes, int n_in,
                              void* d_out, int out_size) {
    const float* fx   = (const float*)d_in[0];
    const float* ln1w = (const float*)d_in[1];
    const float* ln1b = (const float*)d_in[2];
    const float* Wx   = (const float*)d_in[3];
    const float* bx   = (const float*)d_in[4];
    const float* Wqp  = (const float*)d_in[5];
    const float* Wkp  = (const float*)d_in[6];
    const float* Wvp  = (const float*)d_in[7];
    const float* Wo   = (const float*)d_in[8];
    const float* bo   = (const float*)d_in[9];
    const float* ln2w = (const float*)d_in[10];
    const float* ln2b = (const float*)d_in[11];
    const float* W1   = (const float*)d_in[12];
    const float* b1   = (const float*)d_in[13];
    const float* W2   = (const float*)d_in[14];
    const float* b2   = (const float*)d_in[15];
    float* out = (float*)d_out;

    __half *p_xln, *p_qkv, *p_KW, *p_y, *p_hid, *p_WQKV, *p_W1, *p_W2;
    float  *p_h, *p_bqkv;
    cudaGetSymbolAddress((void**)&p_xln,  g_xln_h);
    cudaGetSymbolAddress((void**)&p_qkv,  g_qkv);
    cudaGetSymbolAddress((void**)&p_KW,   g_KW);
    cudaGetSymbolAddress((void**)&p_h,    g_h);
    cudaGetSymbolAddress((void**)&p_y,    g_y_h);
    cudaGetSymbolAddress((void**)&p_hid,  g_hid_h);
    cudaGetSymbolAddress((void**)&p_WQKV, g_WQKV);
    cudaGetSymbolAddress((void**)&p_bqkv, g_bqkv);
    cudaGetSymbolAddress((void**)&p_W1,   g_W1_h);
    cudaGetSymbolAddress((void**)&p_W2,   g_W2_h);

    cudaFuncSetAttribute(hgemm_kernel<0,1>, cudaFuncAttributeMaxDynamicSharedMemorySize, GEMM_SMEM);
    cudaFuncSetAttribute(hgemm_kernel<1,0>, cudaFuncAttributeMaxDynamicSharedMemorySize, GEMM_SMEM);
    cudaFuncSetAttribute(hgemm_kernel<2,1>, cudaFuncAttributeMaxDynamicSharedMemorySize, GEMM_SMEM);

    // 0) weight conversion + composite q/k/v weights
    f2h_all_kernel<<<(F4_TOTAL + 255) / 256, 256>>>(W1, W2, p_W1, p_W2);
    compose_kernel<<<24, 256>>>(Wqp, Wkp, Wvp, Wx, bx, p_WQKV, p_bqkv);

    dim3 lnBlk(32, 8);
    // 1) LN1 -> fp16
    ln_kernel<<<Mq / 8, lnBlk>>>(fx, ln1w, ln1b, p_xln);
    // 2) qkv_logits = xln @ WQKV^T + bqkv  (fp16 out, one fused GEMM)
    hgemm_kernel<0,1><<<dim3(QKVW / BN, Mq / BM, 1), 256, GEMM_SMEM>>>(
        p_xln, p_WQKV, p_bqkv, nullptr, nullptr, p_qkv, QKVW, Cq, Cq, 0, 0, 0);
    // 3) softmax q in place + tensor-core kv partials
    softkv_kernel<<<dim3(KV_CHUNKS, Hq, Bq), 128>>>(p_qkv);
    // 4) finalize kv + KW = kv @ Wo^T (per batch, fp16)
    kvw_kernel<<<BHq, 256>>>(Wo, p_KW);
    // 5) h = q @ KW^T + bo + fx  (batched over b; q read from qkv cols 0..255)
    hgemm_kernel<1,0><<<dim3(Cq / BN, Nq / BM, Bq), 256, GEMM_SMEM>>>(
        p_qkv, p_KW, bo, fx, p_h, nullptr, Cq, Cq, QKVW,
        (size_t)Nq * QKVW, (size_t)Cq * Cq, (size_t)Nq * Cq);
    // 6) LN2 -> fp16
    ln_kernel<<<Mq / 8, lnBlk>>>(p_h, ln2w, ln2b, p_y);
    // 7) hid = gelu(y @ W1^T + b1)  (fp16 out)
    hgemm_kernel<2,1><<<dim3(HIDq / BN, Mq / BM, 1), 256, GEMM_SMEM>>>(
        p_y, p_W1, b1, nullptr, nullptr, p_hid, HIDq, Cq, Cq, 0, 0, 0);
    // 8) out = hid @ W2^T + b2 + h
    hgemm_kernel<1,0><<<dim3(Cq / BN, Mq / BM, 1), 256, GEMM_SMEM>>>(
        p_hid, p_W2, b2, p_h, out, nullptr, Cq, HIDq, HIDq, 0, 0, 0);
}